// round 16
// baseline (speedup 1.0000x reference)
#include <cuda_runtime.h>
#include <cuda_fp16.h>

// ---------------- problem constants ----------------
#define BB   2
#define TTT  2048
#define DM   512
#define NHD  8
#define DHD  64
#define NLAY 4
#define DI   2048
#define CIN  2048
#define NCLS 64
#define MR   (BB * TTT)   // 4096 token rows

// ---------------- scratch (device globals; no allocation allowed) ----------------
__device__ float g_h[(size_t)MR * DM];                 // fp32 residual stream
__device__ float g_tmp[(size_t)MR * DM];
__device__ float g_Bx[(size_t)BB * NHD * TTT * TTT];   // SHIFTED position scores (fp32)
// fp16 tensors
__device__ __half g_x16[(size_t)MR * CIN];
__device__ __half g_h16[(size_t)MR * DM];
__device__ __half g_heads16[(size_t)MR * 3 * DM];      // only K block consumed
__device__ __half g_qw16[(size_t)MR * DM];
__device__ __half g_qr16[(size_t)MR * DM];
__device__ __half g_rk16[(size_t)TTT * NLAY * DM];     // [T][4*512]: all layers' rk
__device__ __half g_pos16[(size_t)TTT * DM];
__device__ __half g_ff16[(size_t)MR * DI];
__device__ __half g_av16[(size_t)MR * DM];
__device__ __half g_vT16[(size_t)DM * BB * TTT];       // [d(512)][b(2)*T] transposed V
// fp16 weights
#define W_EMB  0
#define W_QKV  (W_EMB + DM * CIN)
#define W_RPJ  (W_QKV + NLAY * 3 * DM * DM)
#define W_O    (W_RPJ + NLAY * DM * DM)
#define W_FF1  (W_O + NLAY * DM * DM)
#define W_FF2  (W_FF1 + NLAY * DI * DM)
#define W_CLS  (W_FF2 + NLAY * DM * DI)
#define W_END  (W_CLS + NCLS * DM)
__device__ __half g_w16[(size_t)W_END];

// ---------------- helpers ----------------
__device__ __forceinline__ unsigned packh2(float a, float b) {
    __half2 h = __floats2half2_rn(a, b);
    return *(unsigned*)&h;
}

__device__ __forceinline__ void mma_f16(float* c, unsigned a0, unsigned a1,
                                        unsigned a2, unsigned a3,
                                        unsigned b0, unsigned b1) {
    asm volatile(
        "mma.sync.aligned.m16n8k16.row.col.f32.f16.f16.f32 "
        "{%0,%1,%2,%3}, {%4,%5,%6,%7}, {%8,%9}, {%0,%1,%2,%3};"
        : "+f"(c[0]), "+f"(c[1]), "+f"(c[2]), "+f"(c[3])
        : "r"(a0), "r"(a1), "r"(a2), "r"(a3), "r"(b0), "r"(b1));
}

__device__ __forceinline__ void cp16(void* dst, const void* src, int srcbytes) {
    unsigned u = (unsigned)__cvta_generic_to_shared(dst);
    asm volatile("cp.async.cg.shared.global [%0], [%1], 16, %2;"
                 :: "r"(u), "l"(src), "r"(srcbytes));
}
__device__ __forceinline__ void cp_commit() {
    asm volatile("cp.async.commit_group;");
}

// ---------------- fp32 -> fp16 weight conversion (MLP=4) ----------------
__global__ void __launch_bounds__(256) round_copy16(const float* __restrict__ src,
                                                    __half* __restrict__ dst, int n)
{
    int base = (blockIdx.x * 256 + threadIdx.x) * 16;
    if (base < n) {
        float4 v0 = *(const float4*)(src + base);
        float4 v1 = *(const float4*)(src + base + 4);
        float4 v2 = *(const float4*)(src + base + 8);
        float4 v3 = *(const float4*)(src + base + 12);
        uint2 o0, o1;
        o0.x = packh2(v0.x, v0.y); o0.y = packh2(v0.z, v0.w);
        o1.x = packh2(v1.x, v1.y); o1.y = packh2(v1.z, v1.w);
        *(uint2*)(dst + base) = o0;
        *(uint2*)(dst + base + 4) = o1;
        uint2 o2, o3;
        o2.x = packh2(v2.x, v2.y); o2.y = packh2(v2.z, v2.w);
        o3.x = packh2(v3.x, v3.y); o3.y = packh2(v3.z, v3.w);
        *(uint2*)(dst + base + 8) = o2;
        *(uint2*)(dst + base + 12) = o3;
    }
}

// ---------------- FP16 tensor-core GEMM, 4-stage cp.async, 2 CTAs/SM ----------------
// C[M,N] = A[M,K] @ B[N,K]^T (+fp32 bias)(+relu). Paired-k16 fragments, stride 48 halves.
#define G16_STG (128 * 48)                 // halves per stage per matrix
#define GEMM16_SMEM4 (8 * G16_STG * 2)     // 98304 B (4-stage)
#define GEMM16_SMEM2 (4 * G16_STG * 2)     // 49152 B (2-stage, bd kernel)

__global__ void __launch_bounds__(256, 2) gemm16(
    const __half* __restrict__ A, int lda,
    const __half* __restrict__ B, int ldb,
    const float* __restrict__ bias,
    float* __restrict__ C, int ldc,
    __half* __restrict__ C16, int ldc16, int c16lo, int c16hi,
    int M, int N, int K, int relu,
    const float* __restrict__ rwb, const float* __restrict__ rrb,
    __half* __restrict__ qwO, __half* __restrict__ qrO,
    __half* __restrict__ vTO,
    float* __restrict__ outT)
{
    extern __shared__ __half gs16[];
    __half* AsBase = gs16;                  // [4][G16_STG]
    __half* BsBase = gs16 + 4 * G16_STG;    // [4][G16_STG]

    const int tid = threadIdx.x;
    const int warp = tid >> 5, lane = tid & 31;
    const int wm = warp >> 2, wn = warp & 3;
    const int g = lane >> 2, tg = lane & 3;
    const int m0 = blockIdx.y * 128, n0 = blockIdx.x * 128;

    float acc[4][4][4];
#pragma unroll
    for (int mt = 0; mt < 4; mt++)
#pragma unroll
        for (int nt = 0; nt < 4; nt++)
#pragma unroll
            for (int i = 0; i < 4; i++) acc[mt][nt][i] = 0.f;

    const int KT = K >> 5;

    auto load_stage = [&](int st, int k0) {
#pragma unroll
        for (int i = 0; i < 2; i++) {
            int idx = tid + i * 256;
            int row = idx >> 2;
            int kq = (idx & 3) * 8;
            cp16(AsBase + st * G16_STG + row * 48 + kq,
                 A + (size_t)(m0 + row) * lda + k0 + kq, 16);
        }
#pragma unroll
        for (int i = 0; i < 2; i++) {
            int idx = tid + i * 256;
            int row = idx >> 2;
            int kq = (idx & 3) * 8;
            int ok = (n0 + row) < N;
            cp16(BsBase + st * G16_STG + row * 48 + kq,
                 B + (size_t)(ok ? (n0 + row) : 0) * ldb + k0 + kq, ok ? 16 : 0);
        }
        cp_commit();
    };

    load_stage(0, 0);
    if (KT > 1) load_stage(1, 32);
    if (KT > 2) load_stage(2, 64);

    for (int kt = 0; kt < KT; kt++) {
        const int st = kt & 3;
        if (kt + 3 < KT) {
            load_stage((kt + 3) & 3, (kt + 3) * 32);
            asm volatile("cp.async.wait_group 3;");
        } else if (kt + 2 < KT) {
            asm volatile("cp.async.wait_group 2;");
        } else if (kt + 1 < KT) {
            asm volatile("cp.async.wait_group 1;");
        } else {
            asm volatile("cp.async.wait_group 0;");
        }
        __syncthreads();

        const __half* Asl = AsBase + st * G16_STG;
        const __half* Bsl = BsBase + st * G16_STG;

#pragma unroll
        for (int ks = 0; ks < 2; ks++) {
            const int kk = ks * 16 + 4 * tg;
            uint2 ua[4][2];
            uint2 vb[4];
#pragma unroll
            for (int mt = 0; mt < 4; mt++) {
                int r = wm * 64 + mt * 16;
                ua[mt][0] = *(const uint2*)(Asl + (r + g) * 48 + kk);
                ua[mt][1] = *(const uint2*)(Asl + (r + g + 8) * 48 + kk);
            }
#pragma unroll
            for (int nt = 0; nt < 4; nt++) {
                int c = wn * 32 + nt * 8;
                vb[nt] = *(const uint2*)(Bsl + (c + g) * 48 + kk);
            }
#pragma unroll
            for (int mt = 0; mt < 4; mt++)
#pragma unroll
                for (int nt = 0; nt < 4; nt++)
                    mma_f16(acc[mt][nt], ua[mt][0].x, ua[mt][1].x,
                            ua[mt][0].y, ua[mt][1].y, vb[nt].x, vb[nt].y);
        }
        __syncthreads();
    }

#pragma unroll
    for (int mt = 0; mt < 4; mt++) {
        int r0 = m0 + wm * 64 + mt * 16 + g;
#pragma unroll
        for (int nt = 0; nt < 4; nt++) {
            int c0 = n0 + wn * 32 + nt * 8 + tg * 2;
            if (c0 < N) {
                float b0v = bias ? bias[c0] : 0.f;
                float b1v = bias ? bias[c0 + 1] : 0.f;
                float v0 = acc[mt][nt][0] + b0v;
                float v1 = acc[mt][nt][1] + b1v;
                float v2 = acc[mt][nt][2] + b0v;
                float v3 = acc[mt][nt][3] + b1v;
                if (relu) {
                    v0 = fmaxf(v0, 0.f); v1 = fmaxf(v1, 0.f);
                    v2 = fmaxf(v2, 0.f); v3 = fmaxf(v3, 0.f);
                }
                if (C) {
                    *(float2*)(C + (size_t)r0 * ldc + c0) = make_float2(v0, v1);
                    *(float2*)(C + (size_t)(r0 + 8) * ldc + c0) = make_float2(v2, v3);
                }
                if (C16 && c0 >= c16lo && c0 < c16hi) {
                    *(unsigned*)(C16 + (size_t)r0 * ldc16 + c0) = packh2(v0, v1);
                    *(unsigned*)(C16 + (size_t)(r0 + 8) * ldc16 + c0) = packh2(v2, v3);
                }
                if (qwO && c0 < DM) {
                    float w0 = rwb[c0], w1 = rwb[c0 + 1];
                    float r0b = rrb[c0], r1b = rrb[c0 + 1];
                    *(unsigned*)(qwO + (size_t)r0 * DM + c0) = packh2(v0 + w0, v1 + w1);
                    *(unsigned*)(qwO + (size_t)(r0 + 8) * DM + c0) = packh2(v2 + w0, v3 + w1);
                    *(unsigned*)(qrO + (size_t)r0 * DM + c0) = packh2(v0 + r0b, v1 + r1b);
                    *(unsigned*)(qrO + (size_t)(r0 + 8) * DM + c0) = packh2(v2 + r0b, v3 + r1b);
                }
                if (vTO && c0 >= 2 * DM) {
                    int d = c0 - 2 * DM;
                    int bb_ = r0 >> 11, t0 = r0 & 2047;
                    __half* vp0 = vTO + (size_t)d * (BB * TTT) + bb_ * TTT;
                    __half* vp1 = vTO + (size_t)(d + 1) * (BB * TTT) + bb_ * TTT;
                    vp0[t0] = __float2half(v0);
                    vp1[t0] = __float2half(v1);
                    vp0[t0 + 8] = __float2half(v2);
                    vp1[t0 + 8] = __float2half(v3);
                }
                if (outT) {
                    int bb_ = r0 >> 11, t0 = r0 & 2047;
                    float* op0 = outT + ((size_t)bb_ * NCLS + c0) * TTT;
                    float* op1 = outT + ((size_t)bb_ * NCLS + c0 + 1) * TTT;
                    op0[t0] = v0;
                    op1[t0] = v1;
                    op0[t0 + 8] = v2;
                    op1[t0 + 8] = v3;
                }
            }
        }
    }
}

// ---------------- BD GEMM (fp16 core) with shifted-scatter fp32 epilogue ----------------
__device__ __forceinline__ void bd_store(float* __restrict__ BDs, int i, int c, float v) {
    int thr = TTT - 1 - i;
    if (c >= thr)      BDs[(size_t)i * TTT + (c - thr)] = v;
    else if (i > 0)    BDs[(size_t)(i - 1) * TTT + (c + i + 1)] = v;
}

__global__ void __launch_bounds__(256, 2) gemm_bd16(
    const __half* __restrict__ A,   // qr16 [MR][512]
    const __half* __restrict__ B,   // rk slice, row stride ldb
    int ldb,
    float* __restrict__ C)          // BDs [16][T][T] fp32
{
    const int z = blockIdx.z, zb = z >> 3, zn = z & 7;
    A += (size_t)zb * TTT * DM + zn * 64;
    B += zn * 64;
    C += (size_t)z * TTT * TTT;

    extern __shared__ __half gs16[];
    __half* AsBase = gs16;
    __half* BsBase = gs16 + 2 * G16_STG;

    const int tid = threadIdx.x;
    const int warp = tid >> 5, lane = tid & 31;
    const int wm = warp >> 2, wn = warp & 3;
    const int g = lane >> 2, tg = lane & 3;
    const int m0 = blockIdx.y * 128, n0 = blockIdx.x * 128;

    float acc[4][4][4];
#pragma unroll
    for (int mt = 0; mt < 4; mt++)
#pragma unroll
        for (int nt = 0; nt < 4; nt++)
#pragma unroll
            for (int i = 0; i < 4; i++) acc[mt][nt][i] = 0.f;

    auto load_stage = [&](int st, int k0) {
#pragma unroll
        for (int i = 0; i < 2; i++) {
            int idx = tid + i * 256;
            int row = idx >> 2;
            int kq = (idx & 3) * 8;
            cp16(AsBase + st * G16_STG + row * 48 + kq,
                 A + (size_t)(m0 + row) * DM + k0 + kq, 16);
        }
#pragma unroll
        for (int i = 0; i < 2; i++) {
            int idx = tid + i * 256;
            int row = idx >> 2;
            int kq = (idx & 3) * 8;
            cp16(BsBase + st * G16_STG + row * 48 + kq,
                 B + (size_t)(n0 + row) * ldb + k0 + kq, 16);
        }
        cp_commit();
    };

    load_stage(0, 0);

#pragma unroll
    for (int kt = 0; kt < 2; kt++) {
        const int st = kt & 1;
        if (kt == 0) {
            load_stage(1, 32);
            asm volatile("cp.async.wait_group 1;");
        } else {
            asm volatile("cp.async.wait_group 0;");
        }
        __syncthreads();

        const __half* Asl = AsBase + st * G16_STG;
        const __half* Bsl = BsBase + st * G16_STG;

#pragma unroll
        for (int ks = 0; ks < 2; ks++) {
            const int kk = ks * 16 + 4 * tg;
            uint2 ua[4][2];
            uint2 vb[4];
#pragma unroll
            for (int mt = 0; mt < 4; mt++) {
                int r = wm * 64 + mt * 16;
                ua[mt][0] = *(const uint2*)(Asl + (r + g) * 48 + kk);
                ua[mt][1] = *(const uint2*)(Asl + (r + g + 8) * 48 + kk);
            }
#pragma unroll
            for (int nt = 0; nt < 4; nt++) {
                int c = wn * 32 + nt * 8;
                vb[nt] = *(const uint2*)(Bsl + (c + g) * 48 + kk);
            }
#pragma unroll
            for (int mt = 0; mt < 4; mt++)
#pragma unroll
                for (int nt = 0; nt < 4; nt++)
                    mma_f16(acc[mt][nt], ua[mt][0].x, ua[mt][1].x,
                            ua[mt][0].y, ua[mt][1].y, vb[nt].x, vb[nt].y);
        }
        __syncthreads();
    }

#pragma unroll
    for (int mt = 0; mt < 4; mt++) {
        int i0r = m0 + wm * 64 + mt * 16 + g;
        int i1r = i0r + 8;
#pragma unroll
        for (int nt = 0; nt < 4; nt++) {
            int c0 = n0 + wn * 32 + nt * 8 + tg * 2;
            bd_store(C, i0r, c0,     acc[mt][nt][0]);
            bd_store(C, i0r, c0 + 1, acc[mt][nt][1]);
            bd_store(C, i1r, c0,     acc[mt][nt][2]);
            bd_store(C, i1r, c0 + 1, acc[mt][nt][3]);
        }
    }
}

// ---------------- fused fp16 flash attention, 256-row Q tile, 16 warps ----------------
#define FP_ELEMS (256 * 80)
#define FK_ELEMS (64 * 80)
#define FA16_SMEM ((FP_ELEMS + 6 * FK_ELEMS) * 2)   // 102400 B

__global__ void __launch_bounds__(512, 1) flash16(
    const __half* __restrict__ qw,
    const __half* __restrict__ hK,
    const __half* __restrict__ vT,
    const float* __restrict__ BDs,
    __half* __restrict__ av,
    float scale)
{
    extern __shared__ __half fsm[];
    __half* sP = fsm;                       // [256][80]
    __half* sK = fsm + FP_ELEMS;            // [3][64][80]
    __half* sV = sK + 3 * FK_ELEMS;         // [3][64][80]

    const int tid = threadIdx.x;
    const int w = tid >> 5, lane = tid & 31;
    const int g = lane >> 2, tg = lane & 3;
    const int i0 = blockIdx.x * 256;
    const int bn = blockIdx.y;
    const int b = bn >> 3, n = bn & 7;

    const __half* Qb = qw + (size_t)(b * TTT) * DM + n * 64;
    const __half* Kb = hK + (size_t)(b * TTT) * (3 * DM) + DM + n * 64;
    const __half* Vb = vT + (size_t)(n * 64) * (BB * TTT) + b * TTT;
    const float* Bb = BDs + (size_t)bn * TTT * TTT;

    auto kv_load = [&](int st, int j0) {
        {
            int row = tid >> 3, c8 = (tid & 7) * 8;     // 512 threads cover 64x64
            cp16(sK + st * FK_ELEMS + row * 80 + c8,
                 Kb + (size_t)(j0 + row) * (3 * DM) + c8, 16);
            cp16(sV + st * FK_ELEMS + row * 80 + c8,
                 Vb + (size_t)row * (BB * TTT) + j0 + c8, 16);
        }
        cp_commit();
    };

    kv_load(0, 0);

    // stage Q: 256 rows x 64 halves = 2048 uint4 slots, 512 threads -> 4 iters
#pragma unroll
    for (int it = 0; it < 4; it++) {
        int idx = tid + it * 512;
        int row = idx >> 3, h8 = (idx & 7) * 8;
        uint4 v = *(const uint4*)(Qb + (size_t)(i0 + row) * DM + h8);
        *(uint4*)(sP + row * 80 + h8) = v;
    }

    kv_load(1, 64);
    __syncthreads();

    const int r0 = 16 * w + g;
    const int iR0 = i0 + r0, iR1 = iR0 + 8;
    const float* BDr0 = Bb + (size_t)iR0 * TTT;
    const float* BDr1 = Bb + (size_t)iR1 * TTT;

    uint2 qa[4][2];
#pragma unroll
    for (int kf = 0; kf < 4; kf++) {
        qa[kf][0] = *(const uint2*)(sP + r0 * 80 + kf * 16 + 4 * tg);
        qa[kf][1] = *(const uint2*)(sP + (r0 + 8) * 80 + kf * 16 + 4 * tg);
    }

    float Oacc[8][4];
#pragma unroll
    for (int nf = 0; nf < 8; nf++)
#pragma unroll
        for (int i = 0; i < 4; i++) Oacc[nf][i] = 0.f;
    float mr0 = -1e30f, mr1 = -1e30f, lr0 = 0.f, lr1 = 0.f;

    const int NT = TTT / 64;
    for (int jt = 0; jt < NT; jt++) {
        const int st = jt % 3;
        const int j0 = jt * 64;
        if (jt + 2 < NT) {
            kv_load((jt + 2) % 3, (jt + 2) * 64);
            asm volatile("cp.async.wait_group 2;");
        } else if (jt + 1 < NT) {
            asm volatile("cp.async.wait_group 1;");
        } else {
            asm volatile("cp.async.wait_group 0;");
        }
        __syncthreads();

        const __half* Ks = sK + st * FK_ELEMS;
        const __half* Vs = sV + st * FK_ELEMS;

        float2 y0v[8], y1v[8];
#pragma unroll
        for (int nf = 0; nf < 8; nf++) {
            int j = j0 + nf * 8 + 2 * tg;
            y0v[nf] = *(const float2*)(BDr0 + j);
            y1v[nf] = *(const float2*)(BDr1 + j);
        }

        float s[8][4];
#pragma unroll
        for (int nf = 0; nf < 8; nf++)
#pragma unroll
            for (int i = 0; i < 4; i++) s[nf][i] = 0.f;
#pragma unroll
        for (int kf = 0; kf < 4; kf++) {
            const int kk = kf * 16 + 4 * tg;
#pragma unroll
            for (int nf = 0; nf < 8; nf++) {
                uint2 vb = *(const uint2*)(Ks + (nf * 8 + g) * 80 + kk);
                mma_f16(s[nf], qa[kf][0].x, qa[kf][1].x, qa[kf][0].y, qa[kf][1].y,
                        vb.x, vb.y);
            }
        }

#pragma unroll
        for (int nf = 0; nf < 8; nf++) {
            int j = j0 + nf * 8 + 2 * tg;
            float b00 = (j     == iR0 + 1) ? 0.f : y0v[nf].x;
            float b01 = (j + 1 == iR0 + 1) ? 0.f : y0v[nf].y;
            float b10 = (j     == iR1 + 1) ? 0.f : y1v[nf].x;
            float b11 = (j + 1 == iR1 + 1) ? 0.f : y1v[nf].y;
            s[nf][0] = (s[nf][0] + b00) * scale;
            s[nf][1] = (s[nf][1] + b01) * scale;
            s[nf][2] = (s[nf][2] + b10) * scale;
            s[nf][3] = (s[nf][3] + b11) * scale;
        }

        float m0 = -1e30f, m1 = -1e30f;
#pragma unroll
        for (int nf = 0; nf < 8; nf++) {
            m0 = fmaxf(m0, fmaxf(s[nf][0], s[nf][1]));
            m1 = fmaxf(m1, fmaxf(s[nf][2], s[nf][3]));
        }
        m0 = fmaxf(m0, __shfl_xor_sync(0xffffffffu, m0, 1));
        m0 = fmaxf(m0, __shfl_xor_sync(0xffffffffu, m0, 2));
        m1 = fmaxf(m1, __shfl_xor_sync(0xffffffffu, m1, 1));
        m1 = fmaxf(m1, __shfl_xor_sync(0xffffffffu, m1, 2));
        float mn0 = fmaxf(mr0, m0), mn1 = fmaxf(mr1, m1);
        float a0 = __expf(mr0 - mn0), a1 = __expf(mr1 - mn1);

        float l0 = 0.f, l1 = 0.f;
#pragma unroll
        for (int nf = 0; nf < 8; nf++) {
            float p0 = __expf(s[nf][0] - mn0);
            float p1 = __expf(s[nf][1] - mn0);
            float p2 = __expf(s[nf][2] - mn1);
            float p3 = __expf(s[nf][3] - mn1);
            l0 += p0 + p1; l1 += p2 + p3;
            int c = nf * 8 + 2 * tg;
            *(unsigned*)(sP + r0 * 80 + c)       = packh2(p0, p1);
            *(unsigned*)(sP + (r0 + 8) * 80 + c) = packh2(p2, p3);
        }
        l0 += __shfl_xor_sync(0xffffffffu, l0, 1);
        l0 += __shfl_xor_sync(0xffffffffu, l0, 2);
        l1 += __shfl_xor_sync(0xffffffffu, l1, 1);
        l1 += __shfl_xor_sync(0xffffffffu, l1, 2);
        lr0 = lr0 * a0 + l0;
        lr1 = lr1 * a1 + l1;
        mr0 = mn0; mr1 = mn1;
#pragma unroll
        for (int nf = 0; nf < 8; nf++) {
            Oacc[nf][0] *= a0; Oacc[nf][1] *= a0;
            Oacc[nf][2] *= a1; Oacc[nf][3] *= a1;
        }
        __syncwarp();

#pragma unroll
        for (int kf = 0; kf < 4; kf++) {
            const int kk = kf * 16 + 4 * tg;
            uint2 pa0 = *(const uint2*)(sP + r0 * 80 + kk);
            uint2 pa1 = *(const uint2*)(sP + (r0 + 8) * 80 + kk);
#pragma unroll
            for (int nf = 0; nf < 8; nf++) {
                uint2 vb = *(const uint2*)(Vs + (nf * 8 + g) * 80 + kk);
                mma_f16(Oacc[nf], pa0.x, pa1.x, pa0.y, pa1.y, vb.x, vb.y);
            }
        }
        __syncthreads();
    }

    float inv0 = 1.f / lr0, inv1 = 1.f / lr1;
#pragma unroll
    for (int nf = 0; nf < 8; nf++) {
        int col = n * 64 + nf * 8 + 2 * tg;
        *(unsigned*)(av + (size_t)(b * TTT + iR0) * DM + col) =
            packh2(Oacc[nf][0] * inv0, Oacc[nf][1] * inv0);
        *(unsigned*)(av + (size_t)(b * TTT + iR1) * DM + col) =
            packh2(Oacc[nf][2] * inv1, Oacc[nf][3] * inv1);
    }
}

// ---------------- residual add + LayerNorm (float4, fp32 stream + fp16 mirror) ----------------
__global__ void __launch_bounds__(128) add_ln(
    float* __restrict__ h, __half* __restrict__ h16, const float* __restrict__ a,
    const float* __restrict__ gs, const float* __restrict__ gb)
{
    const int row = blockIdx.x, tid = threadIdx.x;
    float* hp = h + (size_t)row * DM;
    __half* hp16 = h16 + (size_t)row * DM;
    const float* ap = a + (size_t)row * DM;

    float4 hv = *(const float4*)(hp + tid * 4);
    float4 av4 = *(const float4*)(ap + tid * 4);
    float4 v = make_float4(hv.x + av4.x, hv.y + av4.y, hv.z + av4.z, hv.w + av4.w);
    float s = (v.x + v.y) + (v.z + v.w);

    __shared__ float red[8];
#pragma unroll
    for (int o = 16; o > 0; o >>= 1) s += __shfl_xor_sync(0xffffffffu, s, o);
    if ((tid & 31) == 0) red[tid >> 5] = s;
    __syncthreads();
    float mean = (red[0] + red[1] + red[2] + red[3]) * (1.f / 512.f);

    float dx = v.x - mean, dy = v.y - mean, dz = v.z - mean, dw = v.w - mean;
    float var = (dx * dx + dy * dy) + (dz * dz + dw * dw);
#pragma unroll
    for (int o = 16; o > 0; o >>= 1) var += __shfl_xor_sync(0xffffffffu, var, o);
    if ((tid & 31) == 0) red[4 + (tid >> 5)] = var;
    __syncthreads();
    var = (red[4] + red[5] + red[6] + red[7]) * (1.f / 512.f);
    float rs = rsqrtf(var + 1e-5f);

    float4 gsv = *(const float4*)(gs + tid * 4);
    float4 gbv = *(const float4*)(gb + tid * 4);
    float4 o4;
    o4.x = dx * rs * gsv.x + gbv.x;
    o4.y = dy * rs * gsv.y + gbv.y;
    o4.z = dz * rs * gsv.z + gbv.z;
    o4.w = dw * rs * gsv.w + gbv.w;
    *(float4*)(hp + tid * 4) = o4;
    uint2 o16;
    o16.x = packh2(o4.x, o4.y);
    o16.y = packh2(o4.z, o4.w);
    *(uint2*)(hp16 + tid * 4) = o16;
}

// ---------------- small helpers ----------------
__global__ void __launch_bounds__(256) pos_kernel16(__half* __restrict__ pos)
{
    int p = blockIdx.x;
    int f = threadIdx.x;
    float ps = (float)(TTT - 1 - p);
    float invf = 1.0f / powf(10000.0f, (float)(2 * f) / (float)DM);
    float ang = ps * invf;
    pos[(size_t)p * DM + f]       = __float2half(sinf(ang));
    pos[(size_t)p * DM + 256 + f] = __float2half(cosf(ang));
}

__global__ void transpose_x16(const float* __restrict__ x, __half* __restrict__ xT)
{
    __shared__ float tile[32][33];
    int b = blockIdx.z;
    int t0 = blockIdx.x * 32, c0 = blockIdx.y * 32;
    int tx = threadIdx.x, ty = threadIdx.y;
#pragma unroll
    for (int i = 0; i < 4; i++) {
        int c = c0 + ty + i * 8;
        tile[ty + i * 8][tx] = x[((size_t)b * CIN + c) * TTT + t0 + tx];
    }
    __syncthreads();
#pragma unroll
    for (int i = 0; i < 4; i++) {
        int t = t0 + ty + i * 8;
        xT[((size_t)b * TTT + t) * CIN + c0 + tx] = __float2half(tile[tx][ty + i * 8]);
    }
}

// ---------------- host orchestration ----------------
extern "C" void kernel_launch(void* const* d_in, const int* in_sizes, int n_in,
                              void* d_out, int out_size)
{
    const float* x        = (const float*)d_in[0];
    const float* emb_w    = (const float*)d_in[1];
    const float* emb_b    = (const float*)d_in[2];
    const float* r_w_bias = (const float*)d_in[3];
    const float* r_r_bias = (const float*)d_in[4];
    const float* qkv_w    = (const float*)d_in[5];
    const float* qkv_b    = (const float*)d_in[6];
    const float* r_proj_w = (const float*)d_in[7];
    const float* o_w      = (const float*)d_in[8];
    const float* ln1_s    = (const float*)d_in[9];
    const float* ln1_b    = (const float*)d_in[10];
    const float* ff1_w    = (const float*)d_in[11];
    const float* ff1_b    = (const float*)d_in[12];
    const float* ff2_w    = (const float*)d_in[13];
    const float* ff2_b    = (const float*)d_in[14];
    const float* ln2_s    = (const float*)d_in[15];
    const float* ln2_b    = (const float*)d_in[16];
    const float* cls_w    = (const float*)d_in[17];
    const float* cls_b    = (const float*)d_in[18];
    float* outp = (float*)d_out;

    float *h, *tmp, *Bx;
    __half *x16, *h16, *heads16, *qw16, *qr16, *rk16, *pos16, *ff16, *av16, *vT16, *w16;
    cudaGetSymbolAddress((void**)&h, g_h);
    cudaGetSymbolAddress((void**)&tmp, g_tmp);
    cudaGetSymbolAddress((void**)&Bx, g_Bx);
    cudaGetSymbolAddress((void**)&x16, g_x16);
    cudaGetSymbolAddress((void**)&h16, g_h16);
    cudaGetSymbolAddress((void**)&heads16, g_heads16);
    cudaGetSymbolAddress((void**)&qw16, g_qw16);
    cudaGetSymbolAddress((void**)&qr16, g_qr16);
    cudaGetSymbolAddress((void**)&rk16, g_rk16);
    cudaGetSymbolAddress((void**)&pos16, g_pos16);
    cudaGetSymbolAddress((void**)&ff16, g_ff16);
    cudaGetSymbolAddress((void**)&av16, g_av16);
    cudaGetSymbolAddress((void**)&vT16, g_vT16);
    cudaGetSymbolAddress((void**)&w16, g_w16);

    cudaFuncSetAttribute(gemm16, cudaFuncAttributeMaxDynamicSharedMemorySize, GEMM16_SMEM4);
    cudaFuncSetAttribute(gemm_bd16, cudaFuncAttributeMaxDynamicSharedMemorySize, GEMM16_SMEM2);
    cudaFuncSetAttribute(flash16, cudaFuncAttributeMaxDynamicSharedMemorySize, FA16_SMEM);

    const float scale = 1.0f / 8.0f;

    auto rc = [&](const float* src, __half* dst, int n) {
        round_copy16<<<(n / 16 + 255) / 256, 256>>>(src, dst, n);
    };
    rc(emb_w,    w16 + W_EMB, DM * CIN);
    rc(qkv_w,    w16 + W_QKV, NLAY * 3 * DM * DM);
    rc(r_proj_w, w16 + W_RPJ, NLAY * DM * DM);
    rc(o_w,      w16 + W_O,   NLAY * DM * DM);
    rc(ff1_w,    w16 + W_FF1, NLAY * DI * DM);
    rc(ff2_w,    w16 + W_FF2, NLAY * DM * DI);
    rc(cls_w,    w16 + W_CLS, NCLS * DM);

    transpose_x16<<<dim3(TTT / 32, CIN / 32, BB), dim3(32, 8)>>>(x, x16);
    pos_kernel16<<<TTT, 256>>>(pos16);

    // rk for ALL layers in one GEMM: rk_all[T][4*512]
    gemm16<<<dim3(16, 16), 256, GEMM16_SMEM4>>>(
        pos16, DM, w16 + W_RPJ, DM, nullptr, nullptr, 0,
        rk16, NLAY * DM, 0, NLAY * DM, TTT, NLAY * DM, DM, 0,
        nullptr, nullptr, nullptr, nullptr, nullptr, nullptr);

    // embed: h(+h16) = x16 @ emb_w^T + emb_b
    gemm16<<<dim3(4, 32), 256, GEMM16_SMEM4>>>(
        x16, CIN, w16 + W_EMB, CIN, emb_b, h, DM, h16, DM, 0, DM, MR, DM, CIN, 0,
        nullptr, nullptr, nullptr, nullptr, nullptr, nullptr);

    for (int l = 0; l < NLAY; l++) {
        const __half* qkvW = w16 + W_QKV + (size_t)l * 3 * DM * DM;
        const float*  qkvB = qkv_b + (size_t)l * 3 * DM;
        const __half* oW   = w16 + W_O + (size_t)l * DM * DM;
        const __half* f1W  = w16 + W_FF1 + (size_t)l * DI * DM;
        const float*  f1B  = ff1_b + (size_t)l * DI;
        const __half* f2W  = w16 + W_FF2 + (size_t)l * DM * DI;
        const float*  f2B  = ff2_b + (size_t)l * DM;

        // qkv: heads16 K-block only, qw16/qr16 (Q+biases), vT16 (V transposed)
        gemm16<<<dim3(12, 32), 256, GEMM16_SMEM4>>>(
            h16, DM, qkvW, DM, qkvB, nullptr, 0, heads16, 3 * DM, DM, 2 * DM,
            MR, 3 * DM, DM, 0,
            r_w_bias, r_r_bias, qw16, qr16, vT16, nullptr);

        // BDs = rel_shift(qr @ rk_l^T) scatter-stored fp32
        gemm_bd16<<<dim3(16, 16, BB * NHD), 256, GEMM16_SMEM2>>>(
            qr16, rk16 + (size_t)l * DM, NLAY * DM, Bx);

        // fused attention (256-row Q tiles)
        flash16<<<dim3(TTT / 256, BB * NHD), 512, FA16_SMEM>>>(
            qw16, heads16, vT16, Bx, av16, scale);

        // attn_out = av16 @ o_w^T -> tmp fp32
        gemm16<<<dim3(4, 32), 256, GEMM16_SMEM4>>>(
            av16, DM, oW, DM, nullptr, tmp, DM, nullptr, 0, 0, 0, MR, DM, DM, 0,
            nullptr, nullptr, nullptr, nullptr, nullptr, nullptr);

        add_ln<<<MR, 128>>>(h, h16, tmp, ln1_s + l * DM, ln1_b + l * DM);

        // ff16 = relu(h16 @ ff1^T + b)
        gemm16<<<dim3(16, 32), 256, GEMM16_SMEM4>>>(
            h16, DM, f1W, DM, f1B, nullptr, 0, ff16, DI, 0, DI, MR, DI, DM, 1,
            nullptr, nullptr, nullptr, nullptr, nullptr, nullptr);

        // tmp = ff16 @ ff2^T + b
        gemm16<<<dim3(4, 32), 256, GEMM16_SMEM4>>>(
            ff16, DI, f2W, DI, f2B, tmp, DM, nullptr, 0, 0, 0, MR, DM, DI, 0,
            nullptr, nullptr, nullptr, nullptr, nullptr, nullptr);

        add_ln<<<MR, 128>>>(h, h16, tmp, ln2_s + l * DM, ln2_b + l * DM);
    }

    // cls = h16 @ cls_w^T + b, written directly transposed to out[b][k][t]
    gemm16<<<dim3(1, 32), 256, GEMM16_SMEM4>>>(
        h16, DM, w16 + W_CLS, DM, cls_b, nullptr, 0, nullptr, 0, 0, 0,
        MR, NCLS, DM, 0,
        nullptr, nullptr, nullptr, nullptr, nullptr, outp);
}

// round 17
// speedup vs baseline: 1.0407x; 1.0407x over previous
#include <cuda_runtime.h>
#include <cuda_fp16.h>

// ---------------- problem constants ----------------
#define BB   2
#define TTT  2048
#define DM   512
#define NHD  8
#define DHD  64
#define NLAY 4
#define DI   2048
#define CIN  2048
#define NCLS 64
#define MR   (BB * TTT)   // 4096 token rows

// ---------------- scratch (device globals; no allocation allowed) ----------------
__device__ float g_h[(size_t)MR * DM];                 // fp32 residual stream
__device__ float g_tmp[(size_t)MR * DM];
__device__ float g_Bx[(size_t)BB * NHD * TTT * TTT];   // SHIFTED position scores (fp32)
// fp16 tensors
__device__ __half g_x16[(size_t)MR * CIN];
__device__ __half g_h16[(size_t)MR * DM];
__device__ __half g_heads16[(size_t)MR * 3 * DM];      // only K block consumed
__device__ __half g_qw16[(size_t)MR * DM];
__device__ __half g_qr16[(size_t)MR * DM];
__device__ __half g_rk16[(size_t)TTT * NLAY * DM];     // [T][4*512]: all layers' rk
__device__ __half g_pos16[(size_t)TTT * DM];
__device__ __half g_ff16[(size_t)MR * DI];
__device__ __half g_av16[(size_t)MR * DM];
__device__ __half g_vT16[(size_t)DM * BB * TTT];       // [d(512)][b(2)*T] transposed V
// fp16 weights
#define W_EMB  0
#define W_QKV  (W_EMB + DM * CIN)
#define W_RPJ  (W_QKV + NLAY * 3 * DM * DM)
#define W_O    (W_RPJ + NLAY * DM * DM)
#define W_FF1  (W_O + NLAY * DM * DM)
#define W_FF2  (W_FF1 + NLAY * DI * DM)
#define W_CLS  (W_FF2 + NLAY * DM * DI)
#define W_END  (W_CLS + NCLS * DM)
__device__ __half g_w16[(size_t)W_END];

// ---------------- helpers ----------------
__device__ __forceinline__ unsigned packh2(float a, float b) {
    __half2 h = __floats2half2_rn(a, b);
    return *(unsigned*)&h;
}

__device__ __forceinline__ void mma_f16(float* c, unsigned a0, unsigned a1,
                                        unsigned a2, unsigned a3,
                                        unsigned b0, unsigned b1) {
    asm volatile(
        "mma.sync.aligned.m16n8k16.row.col.f32.f16.f16.f32 "
        "{%0,%1,%2,%3}, {%4,%5,%6,%7}, {%8,%9}, {%0,%1,%2,%3};"
        : "+f"(c[0]), "+f"(c[1]), "+f"(c[2]), "+f"(c[3])
        : "r"(a0), "r"(a1), "r"(a2), "r"(a3), "r"(b0), "r"(b1));
}

__device__ __forceinline__ void cp16(void* dst, const void* src, int srcbytes) {
    unsigned u = (unsigned)__cvta_generic_to_shared(dst);
    asm volatile("cp.async.cg.shared.global [%0], [%1], 16, %2;"
                 :: "r"(u), "l"(src), "r"(srcbytes));
}
__device__ __forceinline__ void cp_commit() {
    asm volatile("cp.async.commit_group;");
}

// ---------------- single-pass fp32 -> fp16 weight conversion (all regions) ----------------
__global__ void __launch_bounds__(256) convert_all(
    const float* __restrict__ s_emb, const float* __restrict__ s_qkv,
    const float* __restrict__ s_rpj, const float* __restrict__ s_o,
    const float* __restrict__ s_ff1, const float* __restrict__ s_ff2,
    const float* __restrict__ s_cls, __half* __restrict__ dst)
{
    int base = (blockIdx.x * 256 + threadIdx.x) * 16;
    if (base >= W_END) return;
    const float* src;
    int off;
    if (base < W_QKV)      { src = s_emb; off = base - W_EMB; }
    else if (base < W_RPJ) { src = s_qkv; off = base - W_QKV; }
    else if (base < W_O)   { src = s_rpj; off = base - W_RPJ; }
    else if (base < W_FF1) { src = s_o;   off = base - W_O; }
    else if (base < W_FF2) { src = s_ff1; off = base - W_FF1; }
    else if (base < W_CLS) { src = s_ff2; off = base - W_FF2; }
    else                   { src = s_cls; off = base - W_CLS; }

    float4 v0 = *(const float4*)(src + off);
    float4 v1 = *(const float4*)(src + off + 4);
    float4 v2 = *(const float4*)(src + off + 8);
    float4 v3 = *(const float4*)(src + off + 12);
    uint2 o0, o1, o2, o3;
    o0.x = packh2(v0.x, v0.y); o0.y = packh2(v0.z, v0.w);
    o1.x = packh2(v1.x, v1.y); o1.y = packh2(v1.z, v1.w);
    o2.x = packh2(v2.x, v2.y); o2.y = packh2(v2.z, v2.w);
    o3.x = packh2(v3.x, v3.y); o3.y = packh2(v3.z, v3.w);
    *(uint2*)(dst + base)      = o0;
    *(uint2*)(dst + base + 4)  = o1;
    *(uint2*)(dst + base + 8)  = o2;
    *(uint2*)(dst + base + 12) = o3;
}

// ---------------- FP16 tensor-core GEMM, 4-stage cp.async, 2 CTAs/SM ----------------
#define G16_STG (128 * 48)                 // halves per stage per matrix
#define GEMM16_SMEM4 (8 * G16_STG * 2)     // 98304 B (4-stage)
#define GEMM16_SMEM2 (4 * G16_STG * 2)     // 49152 B (2-stage, bd kernel)

__global__ void __launch_bounds__(256, 2) gemm16(
    const __half* __restrict__ A, int lda,
    const __half* __restrict__ B, int ldb,
    const float* __restrict__ bias,
    float* __restrict__ C, int ldc,
    __half* __restrict__ C16, int ldc16, int c16lo, int c16hi,
    int M, int N, int K, int relu,
    const float* __restrict__ rwb, const float* __restrict__ rrb,
    __half* __restrict__ qwO, __half* __restrict__ qrO,
    __half* __restrict__ vTO,
    float* __restrict__ outT)
{
    extern __shared__ __half gs16[];
    __half* AsBase = gs16;                  // [4][G16_STG]
    __half* BsBase = gs16 + 4 * G16_STG;    // [4][G16_STG]

    const int tid = threadIdx.x;
    const int warp = tid >> 5, lane = tid & 31;
    const int wm = warp >> 2, wn = warp & 3;
    const int g = lane >> 2, tg = lane & 3;
    const int m0 = blockIdx.y * 128, n0 = blockIdx.x * 128;

    float acc[4][4][4];
#pragma unroll
    for (int mt = 0; mt < 4; mt++)
#pragma unroll
        for (int nt = 0; nt < 4; nt++)
#pragma unroll
            for (int i = 0; i < 4; i++) acc[mt][nt][i] = 0.f;

    const int KT = K >> 5;

    auto load_stage = [&](int st, int k0) {
#pragma unroll
        for (int i = 0; i < 2; i++) {
            int idx = tid + i * 256;
            int row = idx >> 2;
            int kq = (idx & 3) * 8;
            cp16(AsBase + st * G16_STG + row * 48 + kq,
                 A + (size_t)(m0 + row) * lda + k0 + kq, 16);
        }
#pragma unroll
        for (int i = 0; i < 2; i++) {
            int idx = tid + i * 256;
            int row = idx >> 2;
            int kq = (idx & 3) * 8;
            int ok = (n0 + row) < N;
            cp16(BsBase + st * G16_STG + row * 48 + kq,
                 B + (size_t)(ok ? (n0 + row) : 0) * ldb + k0 + kq, ok ? 16 : 0);
        }
        cp_commit();
    };

    load_stage(0, 0);
    if (KT > 1) load_stage(1, 32);
    if (KT > 2) load_stage(2, 64);

    for (int kt = 0; kt < KT; kt++) {
        const int st = kt & 3;
        if (kt + 3 < KT) {
            load_stage((kt + 3) & 3, (kt + 3) * 32);
            asm volatile("cp.async.wait_group 3;");
        } else if (kt + 2 < KT) {
            asm volatile("cp.async.wait_group 2;");
        } else if (kt + 1 < KT) {
            asm volatile("cp.async.wait_group 1;");
        } else {
            asm volatile("cp.async.wait_group 0;");
        }
        __syncthreads();

        const __half* Asl = AsBase + st * G16_STG;
        const __half* Bsl = BsBase + st * G16_STG;

#pragma unroll
        for (int ks = 0; ks < 2; ks++) {
            const int kk = ks * 16 + 4 * tg;
            uint2 ua[4][2];
            uint2 vb[4];
#pragma unroll
            for (int mt = 0; mt < 4; mt++) {
                int r = wm * 64 + mt * 16;
                ua[mt][0] = *(const uint2*)(Asl + (r + g) * 48 + kk);
                ua[mt][1] = *(const uint2*)(Asl + (r + g + 8) * 48 + kk);
            }
#pragma unroll
            for (int nt = 0; nt < 4; nt++) {
                int c = wn * 32 + nt * 8;
                vb[nt] = *(const uint2*)(Bsl + (c + g) * 48 + kk);
            }
#pragma unroll
            for (int mt = 0; mt < 4; mt++)
#pragma unroll
                for (int nt = 0; nt < 4; nt++)
                    mma_f16(acc[mt][nt], ua[mt][0].x, ua[mt][1].x,
                            ua[mt][0].y, ua[mt][1].y, vb[nt].x, vb[nt].y);
        }
        __syncthreads();
    }

#pragma unroll
    for (int mt = 0; mt < 4; mt++) {
        int r0 = m0 + wm * 64 + mt * 16 + g;
#pragma unroll
        for (int nt = 0; nt < 4; nt++) {
            int c0 = n0 + wn * 32 + nt * 8 + tg * 2;
            if (c0 < N) {
                float b0v = bias ? bias[c0] : 0.f;
                float b1v = bias ? bias[c0 + 1] : 0.f;
                float v0 = acc[mt][nt][0] + b0v;
                float v1 = acc[mt][nt][1] + b1v;
                float v2 = acc[mt][nt][2] + b0v;
                float v3 = acc[mt][nt][3] + b1v;
                if (relu) {
                    v0 = fmaxf(v0, 0.f); v1 = fmaxf(v1, 0.f);
                    v2 = fmaxf(v2, 0.f); v3 = fmaxf(v3, 0.f);
                }
                if (C) {
                    *(float2*)(C + (size_t)r0 * ldc + c0) = make_float2(v0, v1);
                    *(float2*)(C + (size_t)(r0 + 8) * ldc + c0) = make_float2(v2, v3);
                }
                if (C16 && c0 >= c16lo && c0 < c16hi) {
                    *(unsigned*)(C16 + (size_t)r0 * ldc16 + c0) = packh2(v0, v1);
                    *(unsigned*)(C16 + (size_t)(r0 + 8) * ldc16 + c0) = packh2(v2, v3);
                }
                if (qwO && c0 < DM) {
                    float w0 = rwb[c0], w1 = rwb[c0 + 1];
                    float r0b = rrb[c0], r1b = rrb[c0 + 1];
                    *(unsigned*)(qwO + (size_t)r0 * DM + c0) = packh2(v0 + w0, v1 + w1);
                    *(unsigned*)(qwO + (size_t)(r0 + 8) * DM + c0) = packh2(v2 + w0, v3 + w1);
                    *(unsigned*)(qrO + (size_t)r0 * DM + c0) = packh2(v0 + r0b, v1 + r1b);
                    *(unsigned*)(qrO + (size_t)(r0 + 8) * DM + c0) = packh2(v2 + r0b, v3 + r1b);
                }
                if (vTO && c0 >= 2 * DM) {
                    int d = c0 - 2 * DM;
                    int bb_ = r0 >> 11, t0 = r0 & 2047;
                    __half* vp0 = vTO + (size_t)d * (BB * TTT) + bb_ * TTT;
                    __half* vp1 = vTO + (size_t)(d + 1) * (BB * TTT) + bb_ * TTT;
                    vp0[t0] = __float2half(v0);
                    vp1[t0] = __float2half(v1);
                    vp0[t0 + 8] = __float2half(v2);
                    vp1[t0 + 8] = __float2half(v3);
                }
                if (outT) {
                    int bb_ = r0 >> 11, t0 = r0 & 2047;
                    float* op0 = outT + ((size_t)bb_ * NCLS + c0) * TTT;
                    float* op1 = outT + ((size_t)bb_ * NCLS + c0 + 1) * TTT;
                    op0[t0] = v0;
                    op1[t0] = v1;
                    op0[t0 + 8] = v2;
                    op1[t0 + 8] = v3;
                }
            }
        }
    }
}

// ---------------- BD GEMM (fp16 core) with shifted-scatter fp32 epilogue ----------------
__device__ __forceinline__ void bd_store(float* __restrict__ BDs, int i, int c, float v) {
    int thr = TTT - 1 - i;
    if (c >= thr)      BDs[(size_t)i * TTT + (c - thr)] = v;
    else if (i > 0)    BDs[(size_t)(i - 1) * TTT + (c + i + 1)] = v;
}

__global__ void __launch_bounds__(256, 2) gemm_bd16(
    const __half* __restrict__ A,   // qr16 [MR][512]
    const __half* __restrict__ B,   // rk slice, row stride ldb
    int ldb,
    float* __restrict__ C)          // BDs [16][T][T] fp32
{
    const int z = blockIdx.z, zb = z >> 3, zn = z & 7;
    A += (size_t)zb * TTT * DM + zn * 64;
    B += zn * 64;
    C += (size_t)z * TTT * TTT;

    extern __shared__ __half gs16[];
    __half* AsBase = gs16;
    __half* BsBase = gs16 + 2 * G16_STG;

    const int tid = threadIdx.x;
    const int warp = tid >> 5, lane = tid & 31;
    const int wm = warp >> 2, wn = warp & 3;
    const int g = lane >> 2, tg = lane & 3;
    const int m0 = blockIdx.y * 128, n0 = blockIdx.x * 128;

    float acc[4][4][4];
#pragma unroll
    for (int mt = 0; mt < 4; mt++)
#pragma unroll
        for (int nt = 0; nt < 4; nt++)
#pragma unroll
            for (int i = 0; i < 4; i++) acc[mt][nt][i] = 0.f;

    auto load_stage = [&](int st, int k0) {
#pragma unroll
        for (int i = 0; i < 2; i++) {
            int idx = tid + i * 256;
            int row = idx >> 2;
            int kq = (idx & 3) * 8;
            cp16(AsBase + st * G16_STG + row * 48 + kq,
                 A + (size_t)(m0 + row) * DM + k0 + kq, 16);
        }
#pragma unroll
        for (int i = 0; i < 2; i++) {
            int idx = tid + i * 256;
            int row = idx >> 2;
            int kq = (idx & 3) * 8;
            cp16(BsBase + st * G16_STG + row * 48 + kq,
                 B + (size_t)(n0 + row) * ldb + k0 + kq, 16);
        }
        cp_commit();
    };

    load_stage(0, 0);

#pragma unroll
    for (int kt = 0; kt < 2; kt++) {
        const int st = kt & 1;
        if (kt == 0) {
            load_stage(1, 32);
            asm volatile("cp.async.wait_group 1;");
        } else {
            asm volatile("cp.async.wait_group 0;");
        }
        __syncthreads();

        const __half* Asl = AsBase + st * G16_STG;
        const __half* Bsl = BsBase + st * G16_STG;

#pragma unroll
        for (int ks = 0; ks < 2; ks++) {
            const int kk = ks * 16 + 4 * tg;
            uint2 ua[4][2];
            uint2 vb[4];
#pragma unroll
            for (int mt = 0; mt < 4; mt++) {
                int r = wm * 64 + mt * 16;
                ua[mt][0] = *(const uint2*)(Asl + (r + g) * 48 + kk);
                ua[mt][1] = *(const uint2*)(Asl + (r + g + 8) * 48 + kk);
            }
#pragma unroll
            for (int nt = 0; nt < 4; nt++) {
                int c = wn * 32 + nt * 8;
                vb[nt] = *(const uint2*)(Bsl + (c + g) * 48 + kk);
            }
#pragma unroll
            for (int mt = 0; mt < 4; mt++)
#pragma unroll
                for (int nt = 0; nt < 4; nt++)
                    mma_f16(acc[mt][nt], ua[mt][0].x, ua[mt][1].x,
                            ua[mt][0].y, ua[mt][1].y, vb[nt].x, vb[nt].y);
        }
        __syncthreads();
    }

#pragma unroll
    for (int mt = 0; mt < 4; mt++) {
        int i0r = m0 + wm * 64 + mt * 16 + g;
        int i1r = i0r + 8;
#pragma unroll
        for (int nt = 0; nt < 4; nt++) {
            int c0 = n0 + wn * 32 + nt * 8 + tg * 2;
            bd_store(C, i0r, c0,     acc[mt][nt][0]);
            bd_store(C, i0r, c0 + 1, acc[mt][nt][1]);
            bd_store(C, i1r, c0,     acc[mt][nt][2]);
            bd_store(C, i1r, c0 + 1, acc[mt][nt][3]);
        }
    }
}

// ---------------- fused fp16 flash attention, 3-stage KV, 2 CTAs/SM (128-row tile) ----------------
#define FP_ELEMS (128 * 80)
#define FK_ELEMS (64 * 80)
#define FA16_SMEM ((FP_ELEMS + 6 * FK_ELEMS) * 2)   // 81920 B

__global__ void __launch_bounds__(256, 2) flash16(
    const __half* __restrict__ qw,
    const __half* __restrict__ hK,
    const __half* __restrict__ vT,
    const float* __restrict__ BDs,
    __half* __restrict__ av,
    float scale)
{
    extern __shared__ __half fsm[];
    __half* sP = fsm;
    __half* sK = fsm + FP_ELEMS;
    __half* sV = sK + 3 * FK_ELEMS;

    const int tid = threadIdx.x;
    const int w = tid >> 5, lane = tid & 31;
    const int g = lane >> 2, tg = lane & 3;
    const int i0 = blockIdx.x * 128;
    const int bn = blockIdx.y;
    const int b = bn >> 3, n = bn & 7;

    const __half* Qb = qw + (size_t)(b * TTT) * DM + n * 64;
    const __half* Kb = hK + (size_t)(b * TTT) * (3 * DM) + DM + n * 64;
    const __half* Vb = vT + (size_t)(n * 64) * (BB * TTT) + b * TTT;
    const float* Bb = BDs + (size_t)bn * TTT * TTT;

    auto kv_load = [&](int st, int j0) {
#pragma unroll
        for (int it = 0; it < 2; it++) {
            int idx = tid + it * 256;
            int row = idx >> 3, c8 = (idx & 7) * 8;
            cp16(sK + st * FK_ELEMS + row * 80 + c8,
                 Kb + (size_t)(j0 + row) * (3 * DM) + c8, 16);
        }
#pragma unroll
        for (int it = 0; it < 2; it++) {
            int idx = tid + it * 256;
            int row = idx >> 3, c8 = (idx & 7) * 8;
            cp16(sV + st * FK_ELEMS + row * 80 + c8,
                 Vb + (size_t)row * (BB * TTT) + j0 + c8, 16);
        }
        cp_commit();
    };

    kv_load(0, 0);

#pragma unroll
    for (int it = 0; it < 4; it++) {
        int idx = tid + it * 256;
        int row = idx >> 3, h8 = (idx & 7) * 8;
        uint4 v = *(const uint4*)(Qb + (size_t)(i0 + row) * DM + h8);
        *(uint4*)(sP + row * 80 + h8) = v;
    }

    kv_load(1, 64);
    __syncthreads();

    const int r0 = 16 * w + g;
    const int iR0 = i0 + r0, iR1 = iR0 + 8;
    const float* BDr0 = Bb + (size_t)iR0 * TTT;
    const float* BDr1 = Bb + (size_t)iR1 * TTT;

    uint2 qa[4][2];
#pragma unroll
    for (int kf = 0; kf < 4; kf++) {
        qa[kf][0] = *(const uint2*)(sP + r0 * 80 + kf * 16 + 4 * tg);
        qa[kf][1] = *(const uint2*)(sP + (r0 + 8) * 80 + kf * 16 + 4 * tg);
    }

    float Oacc[8][4];
#pragma unroll
    for (int nf = 0; nf < 8; nf++)
#pragma unroll
        for (int i = 0; i < 4; i++) Oacc[nf][i] = 0.f;
    float mr0 = -1e30f, mr1 = -1e30f, lr0 = 0.f, lr1 = 0.f;

    const int NT = TTT / 64;
    for (int jt = 0; jt < NT; jt++) {
        const int st = jt % 3;
        const int j0 = jt * 64;
        if (jt + 2 < NT) {
            kv_load((jt + 2) % 3, (jt + 2) * 64);
            asm volatile("cp.async.wait_group 2;");
        } else if (jt + 1 < NT) {
            asm volatile("cp.async.wait_group 1;");
        } else {
            asm volatile("cp.async.wait_group 0;");
        }
        __syncthreads();

        const __half* Ks = sK + st * FK_ELEMS;
        const __half* Vs = sV + st * FK_ELEMS;

        float2 y0v[8], y1v[8];
#pragma unroll
        for (int nf = 0; nf < 8; nf++) {
            int j = j0 + nf * 8 + 2 * tg;
            y0v[nf] = *(const float2*)(BDr0 + j);
            y1v[nf] = *(const float2*)(BDr1 + j);
        }

        float s[8][4];
#pragma unroll
        for (int nf = 0; nf < 8; nf++)
#pragma unroll
            for (int i = 0; i < 4; i++) s[nf][i] = 0.f;
#pragma unroll
        for (int kf = 0; kf < 4; kf++) {
            const int kk = kf * 16 + 4 * tg;
#pragma unroll
            for (int nf = 0; nf < 8; nf++) {
                uint2 vb = *(const uint2*)(Ks + (nf * 8 + g) * 80 + kk);
                mma_f16(s[nf], qa[kf][0].x, qa[kf][1].x, qa[kf][0].y, qa[kf][1].y,
                        vb.x, vb.y);
            }
        }

#pragma unroll
        for (int nf = 0; nf < 8; nf++) {
            int j = j0 + nf * 8 + 2 * tg;
            float b00 = (j     == iR0 + 1) ? 0.f : y0v[nf].x;
            float b01 = (j + 1 == iR0 + 1) ? 0.f : y0v[nf].y;
            float b10 = (j     == iR1 + 1) ? 0.f : y1v[nf].x;
            float b11 = (j + 1 == iR1 + 1) ? 0.f : y1v[nf].y;
            s[nf][0] = (s[nf][0] + b00) * scale;
            s[nf][1] = (s[nf][1] + b01) * scale;
            s[nf][2] = (s[nf][2] + b10) * scale;
            s[nf][3] = (s[nf][3] + b11) * scale;
        }

        float m0 = -1e30f, m1 = -1e30f;
#pragma unroll
        for (int nf = 0; nf < 8; nf++) {
            m0 = fmaxf(m0, fmaxf(s[nf][0], s[nf][1]));
            m1 = fmaxf(m1, fmaxf(s[nf][2], s[nf][3]));
        }
        m0 = fmaxf(m0, __shfl_xor_sync(0xffffffffu, m0, 1));
        m0 = fmaxf(m0, __shfl_xor_sync(0xffffffffu, m0, 2));
        m1 = fmaxf(m1, __shfl_xor_sync(0xffffffffu, m1, 1));
        m1 = fmaxf(m1, __shfl_xor_sync(0xffffffffu, m1, 2));
        float mn0 = fmaxf(mr0, m0), mn1 = fmaxf(mr1, m1);
        float a0 = __expf(mr0 - mn0), a1 = __expf(mr1 - mn1);

        float l0 = 0.f, l1 = 0.f;
#pragma unroll
        for (int nf = 0; nf < 8; nf++) {
            float p0 = __expf(s[nf][0] - mn0);
            float p1 = __expf(s[nf][1] - mn0);
            float p2 = __expf(s[nf][2] - mn1);
            float p3 = __expf(s[nf][3] - mn1);
            l0 += p0 + p1; l1 += p2 + p3;
            int c = nf * 8 + 2 * tg;
            *(unsigned*)(sP + r0 * 80 + c)       = packh2(p0, p1);
            *(unsigned*)(sP + (r0 + 8) * 80 + c) = packh2(p2, p3);
        }
        l0 += __shfl_xor_sync(0xffffffffu, l0, 1);
        l0 += __shfl_xor_sync(0xffffffffu, l0, 2);
        l1 += __shfl_xor_sync(0xffffffffu, l1, 1);
        l1 += __shfl_xor_sync(0xffffffffu, l1, 2);
        lr0 = lr0 * a0 + l0;
        lr1 = lr1 * a1 + l1;
        mr0 = mn0; mr1 = mn1;
#pragma unroll
        for (int nf = 0; nf < 8; nf++) {
            Oacc[nf][0] *= a0; Oacc[nf][1] *= a0;
            Oacc[nf][2] *= a1; Oacc[nf][3] *= a1;
        }
        __syncwarp();

#pragma unroll
        for (int kf = 0; kf < 4; kf++) {
            const int kk = kf * 16 + 4 * tg;
            uint2 pa0 = *(const uint2*)(sP + r0 * 80 + kk);
            uint2 pa1 = *(const uint2*)(sP + (r0 + 8) * 80 + kk);
#pragma unroll
            for (int nf = 0; nf < 8; nf++) {
                uint2 vb = *(const uint2*)(Vs + (nf * 8 + g) * 80 + kk);
                mma_f16(Oacc[nf], pa0.x, pa1.x, pa0.y, pa1.y, vb.x, vb.y);
            }
        }
        __syncthreads();
    }

    float inv0 = 1.f / lr0, inv1 = 1.f / lr1;
#pragma unroll
    for (int nf = 0; nf < 8; nf++) {
        int col = n * 64 + nf * 8 + 2 * tg;
        *(unsigned*)(av + (size_t)(b * TTT + iR0) * DM + col) =
            packh2(Oacc[nf][0] * inv0, Oacc[nf][1] * inv0);
        *(unsigned*)(av + (size_t)(b * TTT + iR1) * DM + col) =
            packh2(Oacc[nf][2] * inv1, Oacc[nf][3] * inv1);
    }
}

// ---------------- residual add + LayerNorm (float4, fp32 stream + fp16 mirror) ----------------
__global__ void __launch_bounds__(128) add_ln(
    float* __restrict__ h, __half* __restrict__ h16, const float* __restrict__ a,
    const float* __restrict__ gs, const float* __restrict__ gb)
{
    const int row = blockIdx.x, tid = threadIdx.x;
    float* hp = h + (size_t)row * DM;
    __half* hp16 = h16 + (size_t)row * DM;
    const float* ap = a + (size_t)row * DM;

    float4 hv = *(const float4*)(hp + tid * 4);
    float4 av4 = *(const float4*)(ap + tid * 4);
    float4 v = make_float4(hv.x + av4.x, hv.y + av4.y, hv.z + av4.z, hv.w + av4.w);
    float s = (v.x + v.y) + (v.z + v.w);

    __shared__ float red[8];
#pragma unroll
    for (int o = 16; o > 0; o >>= 1) s += __shfl_xor_sync(0xffffffffu, s, o);
    if ((tid & 31) == 0) red[tid >> 5] = s;
    __syncthreads();
    float mean = (red[0] + red[1] + red[2] + red[3]) * (1.f / 512.f);

    float dx = v.x - mean, dy = v.y - mean, dz = v.z - mean, dw = v.w - mean;
    float var = (dx * dx + dy * dy) + (dz * dz + dw * dw);
#pragma unroll
    for (int o = 16; o > 0; o >>= 1) var += __shfl_xor_sync(0xffffffffu, var, o);
    if ((tid & 31) == 0) red[4 + (tid >> 5)] = var;
    __syncthreads();
    var = (red[4] + red[5] + red[6] + red[7]) * (1.f / 512.f);
    float rs = rsqrtf(var + 1e-5f);

    float4 gsv = *(const float4*)(gs + tid * 4);
    float4 gbv = *(const float4*)(gb + tid * 4);
    float4 o4;
    o4.x = dx * rs * gsv.x + gbv.x;
    o4.y = dy * rs * gsv.y + gbv.y;
    o4.z = dz * rs * gsv.z + gbv.z;
    o4.w = dw * rs * gsv.w + gbv.w;
    *(float4*)(hp + tid * 4) = o4;
    uint2 o16;
    o16.x = packh2(o4.x, o4.y);
    o16.y = packh2(o4.z, o4.w);
    *(uint2*)(hp16 + tid * 4) = o16;
}

// ---------------- small helpers ----------------
__global__ void __launch_bounds__(256) pos_kernel16(__half* __restrict__ pos)
{
    int p = blockIdx.x;
    int f = threadIdx.x;
    float ps = (float)(TTT - 1 - p);
    float invf = 1.0f / powf(10000.0f, (float)(2 * f) / (float)DM);
    float ang = ps * invf;
    pos[(size_t)p * DM + f]       = __float2half(sinf(ang));
    pos[(size_t)p * DM + 256 + f] = __float2half(cosf(ang));
}

__global__ void transpose_x16(const float* __restrict__ x, __half* __restrict__ xT)
{
    __shared__ float tile[32][33];
    int b = blockIdx.z;
    int t0 = blockIdx.x * 32, c0 = blockIdx.y * 32;
    int tx = threadIdx.x, ty = threadIdx.y;
#pragma unroll
    for (int i = 0; i < 4; i++) {
        int c = c0 + ty + i * 8;
        tile[ty + i * 8][tx] = x[((size_t)b * CIN + c) * TTT + t0 + tx];
    }
    __syncthreads();
#pragma unroll
    for (int i = 0; i < 4; i++) {
        int t = t0 + ty + i * 8;
        xT[((size_t)b * TTT + t) * CIN + c0 + tx] = __float2half(tile[tx][ty + i * 8]);
    }
}

// ---------------- host orchestration ----------------
extern "C" void kernel_launch(void* const* d_in, const int* in_sizes, int n_in,
                              void* d_out, int out_size)
{
    const float* x        = (const float*)d_in[0];
    const float* emb_w    = (const float*)d_in[1];
    const float* emb_b    = (const float*)d_in[2];
    const float* r_w_bias = (const float*)d_in[3];
    const float* r_r_bias = (const float*)d_in[4];
    const float* qkv_w    = (const float*)d_in[5];
    const float* qkv_b    = (const float*)d_in[6];
    const float* r_proj_w = (const float*)d_in[7];
    const float* o_w      = (const float*)d_in[8];
    const float* ln1_s    = (const float*)d_in[9];
    const float* ln1_b    = (const float*)d_in[10];
    const float* ff1_w    = (const float*)d_in[11];
    const float* ff1_b    = (const float*)d_in[12];
    const float* ff2_w    = (const float*)d_in[13];
    const float* ff2_b    = (const float*)d_in[14];
    const float* ln2_s    = (const float*)d_in[15];
    const float* ln2_b    = (const float*)d_in[16];
    const float* cls_w    = (const float*)d_in[17];
    const float* cls_b    = (const float*)d_in[18];
    float* outp = (float*)d_out;

    float *h, *tmp, *Bx;
    __half *x16, *h16, *heads16, *qw16, *qr16, *rk16, *pos16, *ff16, *av16, *vT16, *w16;
    cudaGetSymbolAddress((void**)&h, g_h);
    cudaGetSymbolAddress((void**)&tmp, g_tmp);
    cudaGetSymbolAddress((void**)&Bx, g_Bx);
    cudaGetSymbolAddress((void**)&x16, g_x16);
    cudaGetSymbolAddress((void**)&h16, g_h16);
    cudaGetSymbolAddress((void**)&heads16, g_heads16);
    cudaGetSymbolAddress((void**)&qw16, g_qw16);
    cudaGetSymbolAddress((void**)&qr16, g_qr16);
    cudaGetSymbolAddress((void**)&rk16, g_rk16);
    cudaGetSymbolAddress((void**)&pos16, g_pos16);
    cudaGetSymbolAddress((void**)&ff16, g_ff16);
    cudaGetSymbolAddress((void**)&av16, g_av16);
    cudaGetSymbolAddress((void**)&vT16, g_vT16);
    cudaGetSymbolAddress((void**)&w16, g_w16);

    cudaFuncSetAttribute(gemm16, cudaFuncAttributeMaxDynamicSharedMemorySize, GEMM16_SMEM4);
    cudaFuncSetAttribute(gemm_bd16, cudaFuncAttributeMaxDynamicSharedMemorySize, GEMM16_SMEM2);
    cudaFuncSetAttribute(flash16, cudaFuncAttributeMaxDynamicSharedMemorySize, FA16_SMEM);

    const float scale = 1.0f / 8.0f;

    // all weights -> fp16 in ONE kernel
    convert_all<<<(W_END / 16 + 255) / 256, 256>>>(
        emb_w, qkv_w, r_proj_w, o_w, ff1_w, ff2_w, cls_w, w16);

    transpose_x16<<<dim3(TTT / 32, CIN / 32, BB), dim3(32, 8)>>>(x, x16);
    pos_kernel16<<<TTT, 256>>>(pos16);

    // rk for ALL layers in one GEMM: rk_all[T][4*512]
    gemm16<<<dim3(16, 16), 256, GEMM16_SMEM4>>>(
        pos16, DM, w16 + W_RPJ, DM, nullptr, nullptr, 0,
        rk16, NLAY * DM, 0, NLAY * DM, TTT, NLAY * DM, DM, 0,
        nullptr, nullptr, nullptr, nullptr, nullptr, nullptr);

    // embed: h(+h16) = x16 @ emb_w^T + emb_b
    gemm16<<<dim3(4, 32), 256, GEMM16_SMEM4>>>(
        x16, CIN, w16 + W_EMB, CIN, emb_b, h, DM, h16, DM, 0, DM, MR, DM, CIN, 0,
        nullptr, nullptr, nullptr, nullptr, nullptr, nullptr);

    for (int l = 0; l < NLAY; l++) {
        const __half* qkvW = w16 + W_QKV + (size_t)l * 3 * DM * DM;
        const float*  qkvB = qkv_b + (size_t)l * 3 * DM;
        const __half* oW   = w16 + W_O + (size_t)l * DM * DM;
        const __half* f1W  = w16 + W_FF1 + (size_t)l * DI * DM;
        const float*  f1B  = ff1_b + (size_t)l * DI;
        const __half* f2W  = w16 + W_FF2 + (size_t)l * DM * DI;
        const float*  f2B  = ff2_b + (size_t)l * DM;

        // qkv: heads16 K-block only, qw16/qr16 (Q+biases), vT16 (V transposed)
        gemm16<<<dim3(12, 32), 256, GEMM16_SMEM4>>>(
            h16, DM, qkvW, DM, qkvB, nullptr, 0, heads16, 3 * DM, DM, 2 * DM,
            MR, 3 * DM, DM, 0,
            r_w_bias, r_r_bias, qw16, qr16, vT16, nullptr);

        // BDs = rel_shift(qr @ rk_l^T) scatter-stored fp32
        gemm_bd16<<<dim3(16, 16, BB * NHD), 256, GEMM16_SMEM2>>>(
            qr16, rk16 + (size_t)l * DM, NLAY * DM, Bx);

        // fused attention (128-row Q tiles, proven config)
        flash16<<<dim3(TTT / 128, BB * NHD), 256, FA16_SMEM>>>(
            qw16, heads16, vT16, Bx, av16, scale);

        // attn_out = av16 @ o_w^T -> tmp fp32
        gemm16<<<dim3(4, 32), 256, GEMM16_SMEM4>>>(
            av16, DM, oW, DM, nullptr, tmp, DM, nullptr, 0, 0, 0, MR, DM, DM, 0,
            nullptr, nullptr, nullptr, nullptr, nullptr, nullptr);

        add_ln<<<MR, 128>>>(h, h16, tmp, ln1_s + l * DM, ln1_b + l * DM);

        // ff16 = relu(h16 @ ff1^T + b)
        gemm16<<<dim3(16, 32), 256, GEMM16_SMEM4>>>(
            h16, DM, f1W, DM, f1B, nullptr, 0, ff16, DI, 0, DI, MR, DI, DM, 1,
            nullptr, nullptr, nullptr, nullptr, nullptr, nullptr);

        // tmp = ff16 @ ff2^T + b
        gemm16<<<dim3(4, 32), 256, GEMM16_SMEM4>>>(
            ff16, DI, f2W, DI, f2B, tmp, DM, nullptr, 0, 0, 0, MR, DM, DI, 0,
            nullptr, nullptr, nullptr, nullptr, nullptr, nullptr);

        add_ln<<<MR, 128>>>(h, h16, tmp, ln2_s + l * DM, ln2_b + l * DM);
    }

    // cls = h16 @ cls_w^T + b, written directly transposed to out[b][k][t]
    gemm16<<<dim3(1, 32), 256, GEMM16_SMEM4>>>(
        h16, DM, w16 + W_CLS, DM, cls_b, nullptr, 0, nullptr, 0, 0, 0,
        MR, NCLS, DM, 0,
        nullptr, nullptr, nullptr, nullptr, nullptr, outp);
}